// round 17
// baseline (speedup 1.0000x reference)
#include <cuda_runtime.h>
#include <cuda_bf16.h>
#include <math.h>
#include <stdint.h>

#define NPIX 16384            // 128*128

// ---------------------------------------------------------------------------
// Scratch (static device globals)
// ---------------------------------------------------------------------------
__device__ float g_i2h[2][2 * 192 * NPIX];  // i2h out, double-buffered  50 MB
__device__ float g_h2h[2 * 192 * NPIX];     // ret conv out              25 MB
__device__ float g_f1p0[2][2 * 32 * NPIX];  // f1 input-half, dbl-buf   8.4 MB
__device__ float g_f1p1[2 * 32 * NPIX];     // f1 hidden-half           4.2 MB
__device__ float g_fl [2 *  26 * NPIX];     // flows                    3.4 MB

// bf16-split packed operands (channel pairs per 32-bit word)
__device__ uint32_t g_ysbf_h[2 * 192 * NPIX], g_ysbf_l[2 * 192 * NPIX]; // stem out (c,c+1)
__device__ uint32_t g_hbf_h [2 *  32 * NPIX], g_hbf_l [2 *  32 * NPIX]; // hprev (c,c+1)

// pre-converted weights: layouts match smem consumption order
__device__ uint32_t g_wi2h_h[3 * 4 * 9 * 8 * 64],  g_wi2h_l[3 * 4 * 9 * 8 * 64];
__device__ uint32_t g_wf1_h [2 * 4 * 25 * 8 * 32], g_wf1_l [2 * 4 * 25 * 8 * 32];
__device__ uint32_t g_wfl_h [2 * 25 * 8 * 32],     g_wfl_l [2 * 25 * 8 * 32];
__device__ uint32_t g_wret_h[2 * 13 * 4 * 8 * 96], g_wret_l[2 * 13 * 4 * 8 * 96];

__device__ __forceinline__ float leaky_f(float x) { return x >= 0.f ? x : 0.2f * x; }

// split two floats into packed bf16 hi-pair and lo-pair (v = hi + lo)
__device__ __forceinline__ void split2(float v0, float v1, uint32_t& h, uint32_t& l) {
    __nv_bfloat162 hb = __floats2bfloat162_rn(v0, v1);
    float h0 = __low2float(hb), h1 = __high2float(hb);
    __nv_bfloat162 lb = __floats2bfloat162_rn(v0 - h0, v1 - h1);
    h = *reinterpret_cast<uint32_t*>(&hb);
    l = *reinterpret_cast<uint32_t*>(&lb);
}

#define MMA_BF16(c0,c1,c2,c3, a0,a1,a2,a3, b0,b1)                              \
    asm volatile("mma.sync.aligned.m16n8k16.row.col.f32.bf16.bf16.f32 "        \
        "{%0,%1,%2,%3}, {%4,%5,%6,%7}, {%8,%9}, {%0,%1,%2,%3};"                \
        : "+f"(c0), "+f"(c1), "+f"(c2), "+f"(c3)                               \
        : "r"(a0), "r"(a1), "r"(a2), "r"(a3), "r"(b0), "r"(b1))

// ---------------------------------------------------------------------------
// Weight prep — all four conversions in ONE kernel (run once per launch)
// ---------------------------------------------------------------------------
__global__ void wprep_all_k(const float* __restrict__ wi2h,
                            const float* __restrict__ wi2f,
                            const float* __restrict__ wh2f,
                            const float* __restrict__ wfl,
                            const float* __restrict__ wret)
{
    int idx = blockIdx.x * 256 + threadIdx.x;

    if (idx < 55296) {
        int oc = idx & 63;
        int kp = (idx >> 6) & 7;
        int q  = idx >> 9;
        int tap = q % 9;
        int qc  = q / 9;
        int chunk = qc & 3, ocg = qc >> 2;
        int ic = chunk * 16 + 2 * kp;
        int o  = ocg * 64 + oc;
        float v0 = wi2h[(o * 64 + ic    ) * 9 + tap];
        float v1 = wi2h[(o * 64 + ic + 1) * 9 + tap];
        split2(v0, v1, g_wi2h_h[idx], g_wi2h_l[idx]);
        return;
    }
    idx -= 55296;
    if (idx < 51200) {
        int oc = idx & 31;
        int kp = (idx >> 5) & 7;
        int q  = idx >> 8;
        int tap = q % 25;
        int qc  = q / 25;
        int chunk = qc & 3, src = qc >> 2;
        int ic = chunk * 16 + 2 * kp;
        const float* w = src ? wh2f : wi2f;
        float v0 = w[(oc * 64 + ic    ) * 25 + tap];
        float v1 = w[(oc * 64 + ic + 1) * 25 + tap];
        split2(v0, v1, g_wf1_h[idx], g_wf1_l[idx]);
        return;
    }
    idx -= 51200;
    if (idx < 12800) {
        int oc = idx & 31;
        int kp = (idx >> 5) & 7;
        int q  = idx >> 8;
        int tap = q % 25;
        int chunk = q / 25;
        int ic = chunk * 16 + 2 * kp;
        float v0 = 0.f, v1 = 0.f;
        if (oc < 26) {
            v0 = wfl[(oc * 32 + ic    ) * 25 + tap];
            v1 = wfl[(oc * 32 + ic + 1) * 25 + tap];
        }
        split2(v0, v1, g_wfl_h[idx], g_wfl_l[idx]);
        return;
    }
    idx -= 12800;
    if (idx < 79872) {
        int m  = idx % 96;
        int kp = (idx / 96) & 7;
        int chunk = (idx / 768) & 3;
        int l  = (idx / 3072) % 13;
        int mb = idx / 39936;
        int k  = l * 64 + chunk * 16 + kp * 2;
        float v0 = wret[(mb * 96 + m) * 832 + k];
        float v1 = wret[(mb * 96 + m) * 832 + k + 1];
        split2(v0, v1, g_wret_h[idx], g_wret_l[idx]);
    }
}

// ---------------------------------------------------------------------------
// Stem: conv 3x3 stride 2 pad 1 -> bf16-split
// ---------------------------------------------------------------------------
__global__ __launch_bounds__(256) void stem_k(const float* __restrict__ x,
                                              const float* __restrict__ w,
                                              const float* __restrict__ bias)
{
    __shared__ __align__(16) float sw[54][8];

    int tid = threadIdx.x;
    int oc0 = blockIdx.y * 8;
    int b   = blockIdx.z;

    for (int i = tid; i < 432; i += 256) {
        int oc = i & 7, tap = i >> 3;
        sw[tap][oc] = w[(oc0 + oc) * 54 + tap];
    }
    __syncthreads();

    int pix = blockIdx.x * 256 + tid;
    int oy = pix >> 7, ox = pix & 127;

    float acc[8];
    #pragma unroll
    for (int j = 0; j < 8; j++) acc[j] = bias[oc0 + j];

    #pragma unroll
    for (int ic = 0; ic < 6; ic++) {
        const float* xb = x + (b * 6 + ic) * 65536;
        float in[9];
        #pragma unroll
        for (int ky = 0; ky < 3; ky++) {
            int iy = 2 * oy - 1 + ky;
            #pragma unroll
            for (int kx = 0; kx < 3; kx++) {
                int ix = 2 * ox - 1 + kx;
                bool ok = (iy >= 0) & (iy <= 255) & (ix >= 0) & (ix <= 255);
                in[ky * 3 + kx] = ok ? __ldg(&xb[iy * 256 + ix]) : 0.f;
            }
        }
        #pragma unroll
        for (int k = 0; k < 9; k++) {
            int tap = ic * 9 + k;
            float a[8];
            *(float4*)&a[0] = *(const float4*)&sw[tap][0];
            *(float4*)&a[4] = *(const float4*)&sw[tap][4];
            #pragma unroll
            for (int j = 0; j < 8; j++) acc[j] += in[k] * a[j];
        }
    }
    #pragma unroll
    for (int j = 0; j < 8; j++) acc[j] = leaky_f(acc[j]);

    int pbase = ((b * 384 + oc0) >> 1) * NPIX + pix;
    #pragma unroll
    for (int j = 0; j < 4; j++) {
        uint32_t h, l;
        split2(acc[2 * j], acc[2 * j + 1], h, l);
        g_ysbf_h[pbase + j * NPIX] = h;
        g_ysbf_l[pbase + j * NPIX] = l;
    }
}

// ---------------------------------------------------------------------------
// i2h role body (conv3x3 64->192), plain loader, writes g_i2h[buf].
// smem need: (2*5184 + 2*4416) words = 76.8 KB dynamic.
// ---------------------------------------------------------------------------
__device__ __forceinline__ void i2h_body(uint32_t* sm_u, int xt, int ocg, int b,
                                         int t, int buf, const float* __restrict__ bias)
{
    uint32_t* s_wh = sm_u;
    uint32_t* s_wl = s_wh + 5184;
    uint32_t* s_xh = s_wl + 5184;
    uint32_t* s_xl = s_xh + 4416;

    int tid = threadIdx.x;
    int lane = tid & 31;
    int g  = lane >> 2;
    int t4 = lane & 3;
    int wid = tid >> 5;
    int wm = wid >> 2;
    int wn = wid & 3;
    int ry = wn >> 1;
    int xoff = (wn & 1) * 64;

    int y0 = xt * 2;
    int m0 = ocg * 64;
    const uint32_t* inh = g_ysbf_h + (b * 192 + t * 32) * NPIX;
    const uint32_t* inl = g_ysbf_l + (b * 192 + t * 32) * NPIX;

    float acc[2][8][4];
    #pragma unroll
    for (int mt = 0; mt < 2; mt++)
        #pragma unroll
        for (int nt = 0; nt < 8; nt++)
            #pragma unroll
            for (int i = 0; i < 4; i++) acc[mt][nt][i] = 0.f;

    for (int chunk = 0; chunk < 4; chunk++) {
        __syncthreads();
        int wbase = (ocg * 4 + chunk) * 4608;
        for (int i = tid; i < 4608; i += 256) {
            int smi = (i >> 6) * 72 + (i & 63);
            s_wh[smi] = g_wi2h_h[wbase + i];
            s_wl[smi] = g_wi2h_l[wbase + i];
        }
        int pbase = chunk * 8;
        for (int i = tid; i < 4160; i += 256) {
            int col = i % 130, r = i / 130;
            int row = r & 3, kp = r >> 2;
            int gy = y0 - 1 + row, gx = col - 1;
            uint32_t vh = 0, vl = 0;
            if (gy >= 0 && gy < 128 && gx >= 0 && gx < 128) {
                int off = (pbase + kp) * NPIX + gy * 128 + gx;
                vh = inh[off]; vl = inl[off];
            }
            int si = kp * 552 + row * 136 + col;
            s_xh[si] = vh; s_xl[si] = vl;
        }
        __syncthreads();

        #pragma unroll
        for (int ky = 0; ky < 3; ky++) {
            #pragma unroll
            for (int kx = 0; kx < 3; kx++) {
                int tap = ky * 3 + kx;
                uint32_t ah[2][4], al[2][4];
                #pragma unroll
                for (int mt = 0; mt < 2; mt++) {
                    int mm = wm * 32 + mt * 16 + g;
                    int r0 = (tap * 8 + t4) * 72, r1 = (tap * 8 + t4 + 4) * 72;
                    ah[mt][0] = s_wh[r0 + mm];     ah[mt][1] = s_wh[r0 + mm + 8];
                    ah[mt][2] = s_wh[r1 + mm];     ah[mt][3] = s_wh[r1 + mm + 8];
                    al[mt][0] = s_wl[r0 + mm];     al[mt][1] = s_wl[r0 + mm + 8];
                    al[mt][2] = s_wl[r1 + mm];     al[mt][3] = s_wl[r1 + mm + 8];
                }
                int base = (ry + ky) * 136 + xoff + kx;
                #pragma unroll
                for (int nt = 0; nt < 8; nt++) {
                    int cc = base + nt * 8 + g;
                    uint32_t bh0 = s_xh[t4 * 552 + cc];
                    uint32_t bh1 = s_xh[(t4 + 4) * 552 + cc];
                    uint32_t bl0 = s_xl[t4 * 552 + cc];
                    uint32_t bl1 = s_xl[(t4 + 4) * 552 + cc];
                    #pragma unroll
                    for (int mt = 0; mt < 2; mt++) {
                        float* c = acc[mt][nt];
                        MMA_BF16(c[0], c[1], c[2], c[3],
                                 al[mt][0], al[mt][1], al[mt][2], al[mt][3], bh0, bh1);
                        MMA_BF16(c[0], c[1], c[2], c[3],
                                 ah[mt][0], ah[mt][1], ah[mt][2], ah[mt][3], bl0, bl1);
                        MMA_BF16(c[0], c[1], c[2], c[3],
                                 ah[mt][0], ah[mt][1], ah[mt][2], ah[mt][3], bh0, bh1);
                    }
                }
            }
        }
    }

    int pix0 = (y0 + ry) * 128 + xoff;
    float* ob = g_i2h[buf];
    #pragma unroll
    for (int mt = 0; mt < 2; mt++) {
        int m = m0 + wm * 32 + mt * 16 + g;
        float bb0 = bias[m], bb1 = bias[m + 8];
        float* C0 = &ob[(b * 192 + m    ) * NPIX];
        float* C1 = &ob[(b * 192 + m + 8) * NPIX];
        #pragma unroll
        for (int nt = 0; nt < 8; nt++) {
            int px = pix0 + nt * 8 + t4 * 2;
            *(float2*)&C0[px] = make_float2(acc[mt][nt][0] + bb0, acc[mt][nt][1] + bb0);
            *(float2*)&C1[px] = make_float2(acc[mt][nt][2] + bb1, acc[mt][nt][3] + bb1);
        }
    }
}

// ---------------------------------------------------------------------------
// f1 role body (conv5x5 64->32, one source), writes op. smem 64.5 KB.
// ---------------------------------------------------------------------------
__device__ __forceinline__ void f1_body(uint32_t* sm_u, int xt, int src, int b,
                                        int t, float* __restrict__ op)
{
    uint32_t* s_wh = sm_u;             // [5 kx][8 kp][40]
    uint32_t* s_wl = s_wh + 1600;
    uint32_t* s_xh = s_wl + 1600;      // [8 kp][6 rows x 132], kp stride 808
    uint32_t* s_xl = s_xh + 6464;

    int tid = threadIdx.x;
    int lane = tid & 31;
    int g  = lane >> 2;
    int t4 = lane & 3;
    int wid = tid >> 5;
    int rw = wid >> 2;
    int xoff = (wid & 3) * 32;

    int y0 = xt * 2;
    const uint32_t* inh = src ? (g_hbf_h + b * 32 * NPIX) : (g_ysbf_h + (b * 192 + t * 32) * NPIX);
    const uint32_t* inl = src ? (g_hbf_l + b * 32 * NPIX) : (g_ysbf_l + (b * 192 + t * 32) * NPIX);

    float acc[2][4][4];
    #pragma unroll
    for (int mt = 0; mt < 2; mt++)
        #pragma unroll
        for (int nt = 0; nt < 4; nt++)
            #pragma unroll
            for (int i = 0; i < 4; i++) acc[mt][nt][i] = 0.f;

    for (int chunk = 0; chunk < 4; chunk++) {
        __syncthreads();
        int pbase = chunk * 8;
        for (int i = tid; i < 6336; i += 256) {
            int col = i % 132, r = i / 132;
            int row = r % 6, kp = r / 6;
            int gy = y0 - 2 + row, gx = col - 2;
            uint32_t vh = 0, vl = 0;
            if (gy >= 0 && gy < 128 && gx >= 0 && gx < 128) {
                int off = (pbase + kp) * NPIX + gy * 128 + gx;
                vh = inh[off]; vl = inl[off];
            }
            int si = kp * 808 + row * 132 + col;
            s_xh[si] = vh; s_xl[si] = vl;
        }
        #pragma unroll 1
        for (int ky = 0; ky < 5; ky++) {
            if (ky) __syncthreads();
            int wbase = ((src * 4 + chunk) * 25 + ky * 5) * 256;
            {
                int i = tid;
                #pragma unroll
                for (int r = 0; r < 5; r++) {
                    int smi = (i >> 5) * 40 + (i & 31);
                    s_wh[smi] = g_wf1_h[wbase + i];
                    s_wl[smi] = g_wf1_l[wbase + i];
                    i += 256;
                }
            }
            __syncthreads();

            #pragma unroll
            for (int kx = 0; kx < 5; kx++) {
                uint32_t ah[2][4], al[2][4];
                #pragma unroll
                for (int mt = 0; mt < 2; mt++) {
                    int mm = mt * 16 + g;
                    int r0 = (kx * 8 + t4) * 40, r1 = (kx * 8 + t4 + 4) * 40;
                    ah[mt][0] = s_wh[r0 + mm];     ah[mt][1] = s_wh[r0 + mm + 8];
                    ah[mt][2] = s_wh[r1 + mm];     ah[mt][3] = s_wh[r1 + mm + 8];
                    al[mt][0] = s_wl[r0 + mm];     al[mt][1] = s_wl[r0 + mm + 8];
                    al[mt][2] = s_wl[r1 + mm];     al[mt][3] = s_wl[r1 + mm + 8];
                }
                int base = (rw + ky) * 132 + xoff + kx;
                #pragma unroll
                for (int nt = 0; nt < 4; nt++) {
                    int cc = base + nt * 8 + g;
                    uint32_t bh0 = s_xh[t4 * 808 + cc];
                    uint32_t bh1 = s_xh[(t4 + 4) * 808 + cc];
                    uint32_t bl0 = s_xl[t4 * 808 + cc];
                    uint32_t bl1 = s_xl[(t4 + 4) * 808 + cc];
                    #pragma unroll
                    for (int mt = 0; mt < 2; mt++) {
                        float* c = acc[mt][nt];
                        MMA_BF16(c[0], c[1], c[2], c[3],
                                 al[mt][0], al[mt][1], al[mt][2], al[mt][3], bh0, bh1);
                        MMA_BF16(c[0], c[1], c[2], c[3],
                                 ah[mt][0], ah[mt][1], ah[mt][2], ah[mt][3], bl0, bl1);
                        MMA_BF16(c[0], c[1], c[2], c[3],
                                 ah[mt][0], ah[mt][1], ah[mt][2], ah[mt][3], bh0, bh1);
                    }
                }
            }
        }
    }

    int pix0 = (y0 + rw) * 128 + xoff;
    #pragma unroll
    for (int mt = 0; mt < 2; mt++) {
        int m = mt * 16 + g;
        float* C0 = &op[(b * 32 + m    ) * NPIX];
        float* C1 = &op[(b * 32 + m + 8) * NPIX];
        #pragma unroll
        for (int nt = 0; nt < 4; nt++) {
            int px = pix0 + nt * 8 + t4 * 2;
            *(float2*)&C0[px] = make_float2(acc[mt][nt][0], acc[mt][nt][1]);
            *(float2*)&C1[px] = make_float2(acc[mt][nt][2], acc[mt][nt][3]);
        }
    }
}

// ---------------------------------------------------------------------------
// pre_k: i2h(t) (bid<192) + f1-src0(t) (bid 192..255). grid (256, 1, 2).
// Used upfront (t=0) and in the t=0 slot (t=1).
// ---------------------------------------------------------------------------
#define I2H_SMEM_BYTES ((2 * 5184 + 2 * 4416) * 4)
__global__ __launch_bounds__(256, 2) void pre_k(int t, const float* __restrict__ bias_i2h)
{
    extern __shared__ uint32_t sm_u[];
    int bid = blockIdx.x;
    int b   = blockIdx.z;
    if (bid < 192) {
        i2h_body(sm_u, bid & 63, bid >> 6, b, t, t & 1, bias_i2h);
    } else {
        f1_body(sm_u, bid - 192, 0, b, t, g_f1p0[t & 1]);
    }
}

// ---------------------------------------------------------------------------
// f1h: hidden-half conv5x5 only (t>=1). grid (64, 1, 2).
// ---------------------------------------------------------------------------
#define F1_SMEM_BYTES ((2 * 1600 + 2 * 6464) * 4)
__global__ __launch_bounds__(256, 2) void f1h_k(int t)
{
    extern __shared__ uint32_t sm_u[];
    f1_body(sm_u, blockIdx.x, 1, blockIdx.z, t, g_f1p1);
}

// ---------------------------------------------------------------------------
// flow: conv5x5 32 -> 26 (padded 32); loader fuses f1 combine. 1-row tiles.
// grid (128, 1, 2), smem 56.3 KB, 2 blocks/SM. Reads g_f1p0[t&1] + g_f1p1.
// ---------------------------------------------------------------------------
#define FLOW_SMEM_BYTES ((2 * 1600 + 2 * 5440) * 4)
__global__ __launch_bounds__(256, 2) void flow_k(int t, const float* __restrict__ bias,
                                                 const float* __restrict__ bi,
                                                 const float* __restrict__ bh,
                                                 int first)
{
    extern __shared__ uint32_t sm_u[];
    uint32_t* s_wh = sm_u;
    uint32_t* s_wl = s_wh + 1600;
    uint32_t* s_xh = s_wl + 1600;
    uint32_t* s_xl = s_xh + 5440;
    __shared__ float s_cb[32];

    int tid = threadIdx.x;
    int lane = tid & 31;
    int g  = lane >> 2;
    int t4 = lane & 3;
    int wid = tid >> 5;
    int xoff = wid * 16;

    int y0 = blockIdx.x;
    int b  = blockIdx.z;
    if (tid < 32) s_cb[tid] = bi[tid] + bh[tid];

    const float* p0 = g_f1p0[t & 1] + b * 32 * NPIX;
    const float* p1 = g_f1p1 + b * 32 * NPIX;

    float acc[2][2][4];
    #pragma unroll
    for (int mt = 0; mt < 2; mt++)
        #pragma unroll
        for (int nt = 0; nt < 2; nt++)
            #pragma unroll
            for (int i = 0; i < 4; i++) acc[mt][nt][i] = 0.f;

    for (int chunk = 0; chunk < 2; chunk++) {
        __syncthreads();
        int pbase = chunk * 8;
        for (int i = tid; i < 5280; i += 256) {
            int col = i % 132, r = i / 132;
            int row = r % 5, kp = r / 5;
            int gy = y0 - 2 + row, gx = col - 2;
            uint32_t vh = 0, vl = 0;
            if (gy >= 0 && gy < 128 && gx >= 0 && gx < 128) {
                int c0 = 2 * (pbase + kp);
                int off = gy * 128 + gx;
                const float* q0 = p0 + c0 * NPIX;
                float v0 = q0[off], v1 = q0[NPIX + off];
                if (!first) {
                    const float* q1 = p1 + c0 * NPIX;
                    v0 += q1[off]; v1 += q1[NPIX + off];
                }
                v0 = leaky_f(v0 + s_cb[c0]);
                v1 = leaky_f(v1 + s_cb[c0 + 1]);
                split2(v0, v1, vh, vl);
            }
            int si = kp * 680 + row * 132 + col;
            s_xh[si] = vh; s_xl[si] = vl;
        }
        #pragma unroll 1
        for (int ky = 0; ky < 5; ky++) {
            if (ky) __syncthreads();
            int wbase = (chunk * 25 + ky * 5) * 256;
            {
                int i = tid;
                #pragma unroll
                for (int r = 0; r < 5; r++) {
                    int smi = (i >> 5) * 40 + (i & 31);
                    s_wh[smi] = g_wfl_h[wbase + i];
                    s_wl[smi] = g_wfl_l[wbase + i];
                    i += 256;
                }
            }
            __syncthreads();

            #pragma unroll
            for (int kx = 0; kx < 5; kx++) {
                uint32_t ah[2][4], al[2][4];
                #pragma unroll
                for (int mt = 0; mt < 2; mt++) {
                    int mm = mt * 16 + g;
                    int r0 = (kx * 8 + t4) * 40, r1 = (kx * 8 + t4 + 4) * 40;
                    ah[mt][0] = s_wh[r0 + mm];     ah[mt][1] = s_wh[r0 + mm + 8];
                    ah[mt][2] = s_wh[r1 + mm];     ah[mt][3] = s_wh[r1 + mm + 8];
                    al[mt][0] = s_wl[r0 + mm];     al[mt][1] = s_wl[r0 + mm + 8];
                    al[mt][2] = s_wl[r1 + mm];     al[mt][3] = s_wl[r1 + mm + 8];
                }
                int base = ky * 132 + xoff + kx;
                #pragma unroll
                for (int nt = 0; nt < 2; nt++) {
                    int cc = base + nt * 8 + g;
                    uint32_t bh0 = s_xh[t4 * 680 + cc];
                    uint32_t bh1 = s_xh[(t4 + 4) * 680 + cc];
                    uint32_t bl0 = s_xl[t4 * 680 + cc];
                    uint32_t bl1 = s_xl[(t4 + 4) * 680 + cc];
                    #pragma unroll
                    for (int mt = 0; mt < 2; mt++) {
                        float* c = acc[mt][nt];
                        MMA_BF16(c[0], c[1], c[2], c[3],
                                 al[mt][0], al[mt][1], al[mt][2], al[mt][3], bh0, bh1);
                        MMA_BF16(c[0], c[1], c[2], c[3],
                                 ah[mt][0], ah[mt][1], ah[mt][2], ah[mt][3], bl0, bl1);
                        MMA_BF16(c[0], c[1], c[2], c[3],
                                 ah[mt][0], ah[mt][1], ah[mt][2], ah[mt][3], bh0, bh1);
                    }
                }
            }
        }
    }

    int pix0 = y0 * 128 + xoff;
    #pragma unroll
    for (int mt = 0; mt < 2; mt++) {
        int m = mt * 16 + g;
        #pragma unroll
        for (int nt = 0; nt < 2; nt++) {
            int px = pix0 + nt * 8 + t4 * 2;
            if (m < 26) {
                float bb = bias[m];
                *(float2*)&g_fl[(b * 26 + m) * NPIX + px] =
                    make_float2(acc[mt][nt][0] + bb, acc[mt][nt][1] + bb);
            }
            if (m + 8 < 26) {
                float bb = bias[m + 8];
                *(float2*)&g_fl[(b * 26 + m + 8) * NPIX + px] =
                    make_float2(acc[mt][nt][2] + bb, acc[mt][nt][3] + bb);
            }
        }
    }
}

// ---------------------------------------------------------------------------
// wreti: wret (bid<256) + i2h(t+1) (256..447) + f1-src0(t+1) (448..511).
// grid (512 or 256, 1, 2), dynamic 76.8 KB + ~19.5 KB static, 2 blocks/SM.
// ---------------------------------------------------------------------------
__global__ __launch_bounds__(256, 2) void wreti_k(int t, const float* __restrict__ bias,
                                                  const float* __restrict__ bias_i2h,
                                                  const float* __restrict__ outp)
{
    __shared__ int      s_ci[4][128];
    __shared__ float    s_cw[4][128];
    __shared__ uint32_t s_wh[8 * 104], s_wl[8 * 104];
    __shared__ uint32_t s_bh[8 * 136], s_bl[8 * 136];
    extern __shared__ uint32_t sm_u[];

    int bid = blockIdx.x;
    int b   = blockIdx.z;

    if (bid >= 448) {
        f1_body(sm_u, bid - 448, 0, b, t + 1, g_f1p0[(t + 1) & 1]);
        return;
    }
    if (bid >= 256) {
        int r = bid - 256;
        i2h_body(sm_u, r & 63, r >> 6, b, t + 1, (t + 1) & 1, bias_i2h);
        return;
    }

    int tid = threadIdx.x;
    int lane = tid & 31;
    int g  = lane >> 2;
    int t4 = lane & 3;
    int wid = tid >> 5;
    int wm = wid >> 2;
    int wn = wid & 3;
    int mb = wm * 48;
    int nb = wn * 32;

    int n0 = (bid & 127) * 128;
    int mblk = bid >> 7;
    int m0 = mblk * 96;

    float acc[3][4][4];
    #pragma unroll
    for (int mt = 0; mt < 3; mt++)
        #pragma unroll
        for (int nt = 0; nt < 4; nt++)
            #pragma unroll
            for (int i = 0; i < 4; i++) acc[mt][nt][i] = 0.f;

    const float* hprev = outp + ((b * 6 + (t - 1)) * 64) * NPIX;

    for (int l = 0; l < 13; l++) {
        __syncthreads();
        if (tid < 128) {
            int pg = n0 + tid;
            float u = g_fl[(b * 26 + 2 * l    ) * NPIX + pg];
            float v = g_fl[(b * 26 + 2 * l + 1) * NPIX + pg];
            float sx = (float)(pg & 127) - u;
            float sy = (float)(pg >> 7)  - v;
            float fx = floorf(sx), fy = floorf(sy);
            float wx1 = sx - fx, wx0 = 1.f - wx1;
            float wy1 = sy - fy, wy0 = 1.f - wy1;
            int x0 = (int)fx, y0 = (int)fy;
            int x1 = x0 + 1,  y1 = y0 + 1;
            bool vx0 = (x0 >= 0) & (x0 <= 127);
            bool vx1 = (x1 >= 0) & (x1 <= 127);
            bool vy0 = (y0 >= 0) & (y0 <= 127);
            bool vy1 = (y1 >= 0) & (y1 <= 127);
            int cx0 = min(max(x0, 0), 127), cx1 = min(max(x1, 0), 127);
            int cy0 = min(max(y0, 0), 127), cy1 = min(max(y1, 0), 127);
            s_ci[0][tid] = cy0 * 128 + cx0;
            s_ci[1][tid] = cy0 * 128 + cx1;
            s_ci[2][tid] = cy1 * 128 + cx0;
            s_ci[3][tid] = cy1 * 128 + cx1;
            s_cw[0][tid] = (vx0 && vy0) ? wx0 * wy0 : 0.f;
            s_cw[1][tid] = (vx1 && vy0) ? wx1 * wy0 : 0.f;
            s_cw[2][tid] = (vx0 && vy1) ? wx0 * wy1 : 0.f;
            s_cw[3][tid] = (vx1 && vy1) ? wx1 * wy1 : 0.f;
        }

        for (int chunk = 0; chunk < 4; chunk++) {
            __syncthreads();
            int wbase = ((mblk * 13 + l) * 4 + chunk) * 768;
            #pragma unroll
            for (int r = 0; r < 3; r++) {
                int i = tid + r * 256;
                int smi = (i / 96) * 104 + (i % 96);
                s_wh[smi] = g_wret_h[wbase + i];
                s_wl[smi] = g_wret_l[wbase + i];
            }
            #pragma unroll
            for (int r = 0; r < 4; r++) {
                int j = tid + r * 256;
                int kp = j >> 7, px = j & 127;
                int i00 = s_ci[0][px], i10 = s_ci[1][px];
                int i01 = s_ci[2][px], i11 = s_ci[3][px];
                float w00 = s_cw[0][px], w10 = s_cw[1][px];
                float w01 = s_cw[2][px], w11 = s_cw[3][px];
                const float* h0 = hprev + (chunk * 16 + kp * 2) * NPIX;
                const float* h1 = h0 + NPIX;
                float v0 = w00 * __ldg(&h0[i00]) + w10 * __ldg(&h0[i10])
                         + w01 * __ldg(&h0[i01]) + w11 * __ldg(&h0[i11]);
                float v1 = w00 * __ldg(&h1[i00]) + w10 * __ldg(&h1[i10])
                         + w01 * __ldg(&h1[i01]) + w11 * __ldg(&h1[i11]);
                uint32_t hh, ll;
                split2(v0, v1, hh, ll);
                s_bh[kp * 136 + px] = hh;
                s_bl[kp * 136 + px] = ll;
            }
            __syncthreads();

            uint32_t ah[3][4], al[3][4], bh[4][2], bl[4][2];
            #pragma unroll
            for (int mt = 0; mt < 3; mt++) {
                int mm = mb + mt * 16 + g;
                int r0 = t4 * 104, r1 = (t4 + 4) * 104;
                ah[mt][0] = s_wh[r0 + mm];     ah[mt][1] = s_wh[r0 + mm + 8];
                ah[mt][2] = s_wh[r1 + mm];     ah[mt][3] = s_wh[r1 + mm + 8];
                al[mt][0] = s_wl[r0 + mm];     al[mt][1] = s_wl[r0 + mm + 8];
                al[mt][2] = s_wl[r1 + mm];     al[mt][3] = s_wl[r1 + mm + 8];
            }
            #pragma unroll
            for (int nt = 0; nt < 4; nt++) {
                int nn = nb + nt * 8 + g;
                bh[nt][0] = s_bh[t4 * 136 + nn];
                bh[nt][1] = s_bh[(t4 + 4) * 136 + nn];
                bl[nt][0] = s_bl[t4 * 136 + nn];
                bl[nt][1] = s_bl[(t4 + 4) * 136 + nn];
            }
            #pragma unroll
            for (int mt = 0; mt < 3; mt++)
                #pragma unroll
                for (int nt = 0; nt < 4; nt++) {
                    float* c = acc[mt][nt];
                    MMA_BF16(c[0], c[1], c[2], c[3],
                             al[mt][0], al[mt][1], al[mt][2], al[mt][3],
                             bh[nt][0], bh[nt][1]);
                    MMA_BF16(c[0], c[1], c[2], c[3],
                             ah[mt][0], ah[mt][1], ah[mt][2], ah[mt][3],
                             bl[nt][0], bl[nt][1]);
                    MMA_BF16(c[0], c[1], c[2], c[3],
                             ah[mt][0], ah[mt][1], ah[mt][2], ah[mt][3],
                             bh[nt][0], bh[nt][1]);
                }
        }
    }

    float* C = g_h2h + b * 192 * NPIX;
    #pragma unroll
    for (int mt = 0; mt < 3; mt++) {
        int m = m0 + mb + mt * 16 + g;
        float bb0 = bias[m], bb1 = bias[m + 8];
        #pragma unroll
        for (int nt = 0; nt < 4; nt++) {
            int col = n0 + nb + nt * 8 + t4 * 2;
            float2 o0 = make_float2(acc[mt][nt][0] + bb0, acc[mt][nt][1] + bb0);
            float2 o1 = make_float2(acc[mt][nt][2] + bb1, acc[mt][nt][3] + bb1);
            *(float2*)&C[m * NPIX + col]       = o0;
            *(float2*)&C[(m + 8) * NPIX + col] = o1;
        }
    }
}

// ---------------------------------------------------------------------------
// GRU update: out[b,t] fp32 + bf16-split hidden copy. t=0: h2h = b_ret.
// grid (64, 32, 2), block 256. Reads g_i2h[t&1].
// ---------------------------------------------------------------------------
__global__ void gru_k(int t, int first, const float* __restrict__ bret,
                      float* __restrict__ outp)
{
    int pix = blockIdx.x * 256 + threadIdx.x;
    int c2  = blockIdx.y;
    int b   = blockIdx.z;
    int c   = 2 * c2;
    int base = b * 192 * NPIX;
    const float* ib = g_i2h[t & 1];

    float h01[2];
    #pragma unroll
    for (int j = 0; j < 2; j++) {
        int cj = c + j;
        float ir = ib[base + (cj      ) * NPIX + pix];
        float iu = ib[base + (cj +  64) * NPIX + pix];
        float im = ib[base + (cj + 128) * NPIX + pix];
        float hr, hu, hm;
        if (first) {
            hr = bret[cj]; hu = bret[cj + 64]; hm = bret[cj + 128];
        } else {
            hr = g_h2h[base + (cj      ) * NPIX + pix];
            hu = g_h2h[base + (cj +  64) * NPIX + pix];
            hm = g_h2h[base + (cj + 128) * NPIX + pix];
        }

        float r = 1.f / (1.f + expf(-(ir + hr)));
        float z = 1.f / (1.f + expf(-(iu + hu)));
        float m = leaky_f(im + r * hm);

        float hp = first ? 0.f : outp[((b * 6 + t - 1) * 64 + cj) * NPIX + pix];
        float h  = z * hp + (1.f - z) * m;
        outp[((b * 6 + t) * 64 + cj) * NPIX + pix] = h;
        h01[j] = h;
    }
    uint32_t hw, lw;
    split2(h01[0], h01[1], hw, lw);
    int p = (b * 32 + c2) * NPIX + pix;
    g_hbf_h[p] = hw; g_hbf_l[p] = lw;
}

// ---------------------------------------------------------------------------
// Launch
// ---------------------------------------------------------------------------
extern "C" void kernel_launch(void* const* d_in, const int* in_sizes, int n_in,
                              void* d_out, int out_size)
{
    const float* x      = (const float*)d_in[0];
    const float* w_stem = (const float*)d_in[1];
    const float* b_stem = (const float*)d_in[2];
    const float* w_i2h  = (const float*)d_in[3];
    const float* b_i2h  = (const float*)d_in[4];
    const float* w_i2f  = (const float*)d_in[5];
    const float* b_i2f  = (const float*)d_in[6];
    const float* w_h2f  = (const float*)d_in[7];
    const float* b_h2f  = (const float*)d_in[8];
    const float* w_flow = (const float*)d_in[9];
    const float* b_flow = (const float*)d_in[10];
    const float* w_ret  = (const float*)d_in[11];
    const float* b_ret  = (const float*)d_in[12];
    float* outp = (float*)d_out;

    cudaFuncSetAttribute(pre_k,   cudaFuncAttributeMaxDynamicSharedMemorySize, I2H_SMEM_BYTES);
    cudaFuncSetAttribute(f1h_k,   cudaFuncAttributeMaxDynamicSharedMemorySize, F1_SMEM_BYTES);
    cudaFuncSetAttribute(flow_k,  cudaFuncAttributeMaxDynamicSharedMemorySize, FLOW_SMEM_BYTES);
    cudaFuncSetAttribute(wreti_k, cudaFuncAttributeMaxDynamicSharedMemorySize, I2H_SMEM_BYTES);

    wprep_all_k<<<(199168 + 255) / 256, 256>>>(w_i2h, w_i2f, w_h2f, w_flow, w_ret);

    stem_k<<<dim3(64, 48, 2), 256>>>(x, w_stem, b_stem);

    // i2h(0) + f1-src0(0) upfront
    pre_k<<<dim3(256, 1, 2), 256, I2H_SMEM_BYTES>>>(0, b_i2h);

    for (int t = 0; t < 6; t++) {
        int first = (t == 0) ? 1 : 0;
        if (!first)
            f1h_k<<<dim3(64, 1, 2), 256, F1_SMEM_BYTES>>>(t);
        flow_k<<<dim3(128, 1, 2), 256, FLOW_SMEM_BYTES>>>(t, b_flow, b_i2f, b_h2f, first);
        if (first) {
            // i2h(1) + f1-src0(1) in the empty wret slot
            pre_k<<<dim3(256, 1, 2), 256, I2H_SMEM_BYTES>>>(1, b_i2h);
        } else {
            int nblk = (t < 5) ? 512 : 256;
            wreti_k<<<dim3(nblk, 1, 2), 256, I2H_SMEM_BYTES>>>(t, b_ret, b_i2h, outp);
        }
        gru_k<<<dim3(64, 32, 2), 256>>>(t, first, b_ret, outp);
    }
}